// round 1
// baseline (speedup 1.0000x reference)
#include <cuda_runtime.h>

// GriddingReverse: grid [B,128,128,128] fp32 -> ptcloud [B, 128^3, 3] fp32.
// Interior cell (x,y,z >= 1): weighted average of the 8 corner voxel coords,
// weights = grid values, centered by -S/2, scaled by 2/S. Boundary cells -> 0.
//
// Layout strategy:
//   - one warp per (b, x, y) row; lane t handles the 4 output points z in [4t, 4t+4)
//   - per thread: 4 aligned float4 loads (rows (x-1,y-1),(x-1,y),(x,y-1),(x,y))
//   - the z-1 value for the thread's first point comes from lane t-1 via shfl
//   - per thread: 12 output floats = 3 aligned float4 stores (48-byte stride)

#define S 128
#define EPSF 1e-6f

__global__ void __launch_bounds__(256)
gridding_reverse_kernel(const float4* __restrict__ g4,
                        float4* __restrict__ out4,
                        int nrows)
{
    const int gtid = blockIdx.x * blockDim.x + threadIdx.x;
    const int w = gtid >> 5;   // row id: b*128*128 + x*128 + y
    const int t = gtid & 31;   // lane == z-group (4 points)
    if (w >= nrows) return;

    const int y = w & (S - 1);
    const int x = (w >> 7) & (S - 1);
    const int b = w >> 14;

    const int outBase = w * 96 + t * 3;  // float4 index into output

    if (x == 0 || y == 0) {
        const float4 z4 = make_float4(0.f, 0.f, 0.f, 0.f);
        out4[outBase + 0] = z4;
        out4[outBase + 1] = z4;
        out4[outBase + 2] = z4;
        return;
    }

    // Row base in float4 units: row (b, X, Y) = ((b*S + X)*S + Y) * (S/4)
    const int base = ((b * S + (x - 1)) * S + (y - 1)) * (S / 4);
    const float4* __restrict__ r00 = g4 + base;                 // (x-1, y-1)
    const float4* __restrict__ r01 = r00 + (S / 4);             // (x-1, y  )
    const float4* __restrict__ r10 = r00 + S * (S / 4);         // (x  , y-1)
    const float4* __restrict__ r11 = r10 + (S / 4);             // (x  , y  )

    const float4 B00 = r00[t];
    const float4 B01 = r01[t];
    const float4 B10 = r10[t];
    const float4 B11 = r11[t];

    // z-1 value for point j=0 is lane (t-1)'s .w. Lane 0's result is unused
    // (its first point is the z==0 boundary).
    const float a00 = __shfl_up_sync(0xffffffffu, B00.w, 1);
    const float a01 = __shfl_up_sync(0xffffffffu, B01.w, 1);
    const float a10 = __shfl_up_sync(0xffffffffu, B10.w, 1);
    const float a11 = __shfl_up_sync(0xffffffffu, B11.w, 1);

    const float hi00[4] = {B00.x, B00.y, B00.z, B00.w};
    const float hi01[4] = {B01.x, B01.y, B01.z, B01.w};
    const float hi10[4] = {B10.x, B10.y, B10.z, B10.w};
    const float hi11[4] = {B11.x, B11.y, B11.z, B11.w};
    const float lo00[4] = {a00, B00.x, B00.y, B00.z};
    const float lo01[4] = {a01, B01.x, B01.y, B01.z};
    const float lo10[4] = {a10, B10.x, B10.y, B10.z};
    const float lo11[4] = {a11, B11.x, B11.y, B11.z};

    const float xf = (float)x;
    const float yf = (float)y;
    const float zf0 = (float)(t * 4);
    const float scale = 2.0f / (float)S;     // 0.015625
    const float half = (float)S * 0.5f;      // 64

    float res[12];

#pragma unroll
    for (int j = 0; j < 4; ++j) {
        // per-row lo+hi pair sums
        const float p00 = lo00[j] + hi00[j];
        const float p01 = lo01[j] + hi01[j];
        const float p10 = lo10[j] + hi10[j];
        const float p11 = lo11[j] + hi11[j];

        const float x_lo = p00 + p01;               // rows with dx=0
        const float x_hi = p10 + p11;               // rows with dx=1
        const float y_lo = p00 + p10;               // dy=0
        const float y_hi = p01 + p11;               // dy=1
        const float z_lo = lo00[j] + lo01[j] + lo10[j] + lo11[j];
        const float z_hi = hi00[j] + hi01[j] + hi10[j] + hi11[j];

        const float wsum = x_lo + x_hi + EPSF;
        const float inv = 1.0f / wsum;

        const float zf = zf0 + (float)j;

        float px = ((x_hi * xf + x_lo * (xf - 1.0f)) * inv - half) * scale;
        float py = ((y_hi * yf + y_lo * (yf - 1.0f)) * inv - half) * scale;
        float pz = ((z_hi * zf + z_lo * (zf - 1.0f)) * inv - half) * scale;

        if (t == 0 && j == 0) { px = 0.f; py = 0.f; pz = 0.f; }  // z==0 boundary

        res[j * 3 + 0] = px;
        res[j * 3 + 1] = py;
        res[j * 3 + 2] = pz;
    }

    out4[outBase + 0] = make_float4(res[0], res[1], res[2], res[3]);
    out4[outBase + 1] = make_float4(res[4], res[5], res[6], res[7]);
    out4[outBase + 2] = make_float4(res[8], res[9], res[10], res[11]);
}

extern "C" void kernel_launch(void* const* d_in, const int* in_sizes, int n_in,
                              void* d_out, int out_size)
{
    const float4* g4 = (const float4*)d_in[0];
    float4* o4 = (float4*)d_out;

    const int total = in_sizes[0];          // B * 128^3
    const int nb = total >> 21;             // / 2097152
    const int nrows = nb * S * S;           // one warp per row

    const int threads = 256;
    const long long nthreads = (long long)nrows * 32;
    const int blocks = (int)((nthreads + threads - 1) / threads);

    gridding_reverse_kernel<<<blocks, threads>>>(g4, o4, nrows);
}